// round 10
// baseline (speedup 1.0000x reference)
#include <cuda_runtime.h>
#include <cstdint>

#define N_MAX  100000
#define E_MAXC 3200000
#define E_PAD  (E_MAXC + 8 * N_MAX + 8)   // padded CSR + 8 slack for idx prefetch overread
#define IN_F   512
#define HID    16
#define NCLS   7

typedef unsigned long long ull;

// ---- scratch (no allocations allowed) ----
__device__ int    s_cnt[N_MAX];            // true in-degree (excl. self-loop)
__device__ int    s_row[N_MAX];            // CSR row start (padded layout)
__device__ int    s_cur[N_MAX];            // fill cursor
__device__ int    s_bsum[512];             // per-block totals from scanA
__device__ float  s_dinv[N_MAX];
__device__ float4 s_g1[(N_MAX + 1) * 4];   // [N+1][16]; row N = zeros (sentinel)
__device__ float4 s_g2[(N_MAX + 1) * 2];   // [N+1][8];  row N = zeros (sentinel)
__device__ int    s_csr[E_PAD];            // src indices grouped by dst, pad = n

// ---- f32x2 packed math (sm_100+) ----
#define FMA2(d, a, b, c) asm("fma.rn.f32x2 %0, %1, %2, %3;" : "=l"(d) : "l"(a), "l"(b), "l"(c))
#define ADD2(d, a, b)    asm("add.rn.f32x2 %0, %1, %2;"     : "=l"(d) : "l"(a), "l"(b))
#define MUL2(d, a, b)    asm("mul.rn.f32x2 %0, %1, %2;"     : "=l"(d) : "l"(a), "l"(b))
#define PACK2(d, s)      asm("mov.b64 %0, {%1, %1};"        : "=l"(d) : "r"(__float_as_uint(s)))
#define PACKAB(d, lo, hi) asm("mov.b64 %0, {%1, %2};"       : "=l"(d) : "f"(lo), "f"(hi))

__device__ __forceinline__ float lo32(ull p) { return __uint_as_float((unsigned)p); }
__device__ __forceinline__ float hi32(ull p) { return __uint_as_float((unsigned)(p >> 32)); }

// ================= build =================
// zero cnt, preset CSR with sentinel n, zero sentinel rows of g1/g2
__global__ void k_zero(int n, int csr4) {
    int i = blockIdx.x * blockDim.x + threadIdx.x;
    if (i < n) s_cnt[i] = 0;
    if (i < csr4) ((int4*)s_csr)[i] = make_int4(n, n, n, n);
    if (i < 4) s_g1[(size_t)n * 4 + i] = make_float4(0.f, 0.f, 0.f, 0.f);
    if (i < 2) s_g2[(size_t)n * 2 + i] = make_float4(0.f, 0.f, 0.f, 0.f);
}

__global__ void k_hist(const int* __restrict__ dst, int e) {
    int i = blockIdx.x * blockDim.x + threadIdx.x;
    if (i < e) atomicAdd(&s_cnt[dst[i]], 1);
}

// per-block scan of PADDED counts; also computes dinv (so gemm1 can run next,
// occupying the ncu-profiled launch slot)
__global__ void k_scanA(int n) {
    __shared__ int sh[256];
    const int t = threadIdx.x;
    const int i = blockIdx.x * 256 + t;
    int c = (i < n) ? s_cnt[i] : 0;
    int v = (c + 7) & ~7;
    sh[t] = v;
    __syncthreads();
    #pragma unroll
    for (int off = 1; off < 256; off <<= 1) {
        int add = (t >= off) ? sh[t - off] : 0;
        __syncthreads();
        sh[t] += add;
        __syncthreads();
    }
    if (i < n) {
        s_row[i]  = sh[t] - v;                     // exclusive within block
        s_dinv[i] = rsqrtf((float)(c + 1));        // +1 self-loop
    }
    if (t == 255) s_bsum[blockIdx.x] = sh[255];
}

// finalize row starts (adds cross-block prefix); each block reduces
// s_bsum[0..blockIdx) itself (<=391 ints)
__global__ void k_scanC(int n) {
    __shared__ int red[256];
    const int t = threadIdx.x;
    const int b = blockIdx.x;
    int p = 0;
    for (int j = t; j < b; j += 256) p += s_bsum[j];
    red[t] = p;
    __syncthreads();
    #pragma unroll
    for (int off = 128; off >= 1; off >>= 1) {
        if (t < off) red[t] += red[t + off];
        __syncthreads();
    }
    const int base = red[0];
    const int i = b * 256 + t;
    if (i >= n) return;
    int st = s_row[i] + base;
    s_row[i] = st;
    s_cur[i] = st;
}

__global__ void k_fill(const int* __restrict__ src, const int* __restrict__ dst, int e) {
    int i = blockIdx.x * blockDim.x + threadIdx.x;
    if (i >= e) return;
    int p = atomicAdd(&s_cur[dst[i]], 1);
    s_csr[p] = src[i];
}

// ================= layer-1 GEMM: g1[i] = dinv[i] * (x[i] @ W1) =================
// (R9 measured-best config) Thread-per-row, 8 f32x2 accumulators. W (32KB)
// smem, warp-uniform LDS.128 broadcasts. X in 256x8 tiles via cp.async with a
// 4-buffer, 3-tile-deep pipeline and ONE __syncthreads per tile.
#define G1_ROWS 256

#define STAGE(buf, k0)                                                             \
    {                                                                              \
        _Pragma("unroll")                                                          \
        for (int j = 0; j < 2; j++) {                                              \
            int row  = j * 128 + sr;                                               \
            int grow = rowbase + row;                                              \
            int qp   = sq ^ ((row >> 1) & 1);                                      \
            unsigned dstp = (unsigned)__cvta_generic_to_shared(                    \
                &Xs[(buf) * 2048 + row * 8 + qp * 4]);                             \
            const float* gp = x + (size_t)grow * IN_F + (k0) + sq * 4;             \
            if (grow < n)                                                          \
                asm volatile("cp.async.ca.shared.global [%0], [%1], 16;"           \
                             :: "r"(dstp), "l"(gp));                               \
        }                                                                          \
    }

__global__ void __launch_bounds__(256, 3) k_gemm1(const float* __restrict__ x,
                                                  const float* __restrict__ W1, int n) {
    __shared__ float  Ws[IN_F * HID];   // 32 KB
    __shared__ float4 Xs4[4][512];      // 4 x 8 KB  (total static smem = 64 KB)
    float* Xs = (float*)Xs4;

    const int t = threadIdx.x;
    const int rowbase = blockIdx.x * G1_ROWS;
    const int sr = t >> 1, sq = t & 1;  // staging mapping

    STAGE(0, 0);
    asm volatile("cp.async.commit_group;");
    STAGE(1, 8);
    asm volatile("cp.async.commit_group;");
    STAGE(2, 16);
    asm volatile("cp.async.commit_group;");

    #pragma unroll
    for (int i = 0; i < 8; i++)
        ((float4*)Ws)[i * 256 + t] = ((const float4*)W1)[i * 256 + t];

    ull acc[8] = {0, 0, 0, 0, 0, 0, 0, 0};
    const int ss = (t >> 1) & 1;        // compute-side swizzle for own row (=t)

    #pragma unroll 1
    for (int tile = 0; tile < 64; tile++) {
        asm volatile("cp.async.wait_group 2;");   // group `tile` complete
        __syncthreads();                          // visibility + WAR protection

        const float4* xr = (const float4*)&Xs[(tile & 3) * 2048 + t * 8];
        #pragma unroll
        for (int qq = 0; qq < 2; qq++) {
            float4 xv = xr[qq ^ ss];
            #pragma unroll
            for (int jj = 0; jj < 4; jj++) {
                ull xx;
                PACK2(xx, ((const float*)&xv)[jj]);
                const ulonglong2* wr =
                    (const ulonglong2*)(Ws + (tile * 8 + qq * 4 + jj) * HID);
                ulonglong2 wa = wr[0], wb = wr[1], wc = wr[2], wd = wr[3];
                FMA2(acc[0], xx, wa.x, acc[0]); FMA2(acc[1], xx, wa.y, acc[1]);
                FMA2(acc[2], xx, wb.x, acc[2]); FMA2(acc[3], xx, wb.y, acc[3]);
                FMA2(acc[4], xx, wc.x, acc[4]); FMA2(acc[5], xx, wc.y, acc[5]);
                FMA2(acc[6], xx, wd.x, acc[6]); FMA2(acc[7], xx, wd.y, acc[7]);
            }
        }

        if (tile + 3 < 64) {
            STAGE((tile + 3) & 3, (tile + 3) * 8);
            asm volatile("cp.async.commit_group;");
        }
    }

    const int myrow = rowbase + t;
    if (myrow >= n) return;

    const float di = s_dinv[myrow];
    ull dd;
    PACK2(dd, di);
    #pragma unroll
    for (int jj = 0; jj < 8; jj++) MUL2(acc[jj], acc[jj], dd);

    #pragma unroll
    for (int m = 0; m < 4; m++) {
        float4 v;
        v.x = lo32(acc[2 * m]);     v.y = hi32(acc[2 * m]);
        v.z = lo32(acc[2 * m + 1]); v.w = hi32(acc[2 * m + 1]);
        s_g1[(size_t)myrow * 4 + m] = v;
    }
}

// ================= layer-1 gather + fused mid =================
// 4 lanes per dst node; lane m owns cols [4m,4m+4). Rows padded to mult of 8
// (sentinel = zero row) => tail-free 8-wide loop, MLP=8. Index loads for the
// NEXT iteration issue before this iteration's adds (software pipeline); the
// one-iteration overread stays inside s_csr (+8 slack) and is never consumed.
__global__ void __launch_bounds__(256) k_gather1(const float* __restrict__ b1,
                                                 const float* __restrict__ W2, int n) {
    __shared__ float W2s[HID * NCLS];
    __shared__ float b1s[HID];
    const int t = threadIdx.x;
    if (t < HID * NCLS) W2s[t] = W2[t];
    if (t < HID)        b1s[t] = b1[t];
    __syncthreads();

    const int g = (blockIdx.x * 256 + t) >> 2;
    const int m = t & 3;
    if (g >= n) return;

    const ulonglong2* G1 = (const ulonglong2*)s_g1;
    ulonglong2 acc = G1[(size_t)g * 4 + m];     // self-loop term
    const int cnt  = s_cnt[g];
    const int pcnt = (cnt + 7) & ~7;
    const int* cp  = s_csr + s_row[g];

    int ii[8];
    #pragma unroll
    for (int j = 0; j < 8; j++) ii[j] = __ldg(cp + j);

    for (int it = 0; it < pcnt; it += 8) {
        ulonglong2 v[8];
        #pragma unroll
        for (int j = 0; j < 8; j++) v[j] = __ldg(&G1[(size_t)ii[j] * 4 + m]);
        #pragma unroll
        for (int j = 0; j < 8; j++) ii[j] = __ldg(cp + it + 8 + j);  // prefetch
        #pragma unroll
        for (int j = 0; j < 8; j++) {
            ADD2(acc.x, acc.x, v[j].x);
            ADD2(acc.y, acc.y, v[j].y);
        }
    }

    const float di = s_dinv[g];
    float h[4];
    h[0] = fmaxf(fmaf(di, lo32(acc.x), b1s[m * 4 + 0]), 0.f);
    h[1] = fmaxf(fmaf(di, hi32(acc.x), b1s[m * 4 + 1]), 0.f);
    h[2] = fmaxf(fmaf(di, lo32(acc.y), b1s[m * 4 + 2]), 0.f);
    h[3] = fmaxf(fmaf(di, hi32(acc.y), b1s[m * 4 + 3]), 0.f);

    float u[8] = {0.f, 0.f, 0.f, 0.f, 0.f, 0.f, 0.f, 0.f};
    #pragma unroll
    for (int jj = 0; jj < 4; jj++) {
        const int j = m * 4 + jj;
        #pragma unroll
        for (int c = 0; c < NCLS; c++)
            u[c] = fmaf(h[jj], W2s[j * NCLS + c], u[c]);
    }

    ull p[4];
    PACKAB(p[0], u[0], u[1]);
    PACKAB(p[1], u[2], u[3]);
    PACKAB(p[2], u[4], u[5]);
    PACKAB(p[3], u[6], u[7]);
    #pragma unroll
    for (int off = 1; off <= 2; off <<= 1) {
        #pragma unroll
        for (int q = 0; q < 4; q++) {
            ull o = __shfl_xor_sync(0xffffffffu, p[q], off);
            ADD2(p[q], p[q], o);
        }
    }
    ull dd;
    PACK2(dd, di);
    #pragma unroll
    for (int q = 0; q < 4; q++) MUL2(p[q], p[q], dd);

    if (m == 0) {
        float4 v = make_float4(lo32(p[0]), hi32(p[0]), lo32(p[1]), hi32(p[1]));
        s_g2[(size_t)g * 2 + 0] = v;
    } else if (m == 1) {
        float4 v = make_float4(lo32(p[2]), hi32(p[2]), lo32(p[3]), hi32(p[3]));
        s_g2[(size_t)g * 2 + 1] = v;
    }
}

// ================= layer-2 gather + fused final output =================
__global__ void __launch_bounds__(256) k_gather2(const float* __restrict__ b2,
                                                 float* __restrict__ out, int n) {
    const int t = threadIdx.x;
    const int g = (blockIdx.x * 256 + t) >> 2;
    const int m = t & 3;
    if (g >= n) return;

    const ull* G2 = (const ull*)s_g2;
    ull acc = G2[(size_t)g * 4 + m];            // self-loop term
    const int cnt  = s_cnt[g];
    const int pcnt = (cnt + 7) & ~7;
    const int* cp  = s_csr + s_row[g];

    int ii[8];
    #pragma unroll
    for (int j = 0; j < 8; j++) ii[j] = __ldg(cp + j);

    for (int it = 0; it < pcnt; it += 8) {
        ull v[8];
        #pragma unroll
        for (int j = 0; j < 8; j++) v[j] = __ldg(&G2[(size_t)ii[j] * 4 + m]);
        #pragma unroll
        for (int j = 0; j < 8; j++) ii[j] = __ldg(cp + it + 8 + j);  // prefetch
        #pragma unroll
        for (int j = 0; j < 8; j++) ADD2(acc, acc, v[j]);
    }

    const float di = s_dinv[g];
    const int c0 = m * 2;
    float* orow = out + (size_t)g * NCLS;
    orow[c0] = fmaf(di, lo32(acc), __ldg(b2 + c0));
    if (c0 + 1 < NCLS)
        orow[c0 + 1] = fmaf(di, hi32(acc), __ldg(b2 + c0 + 1));
}

extern "C" void kernel_launch(void* const* d_in, const int* in_sizes, int n_in,
                              void* d_out, int out_size) {
    const float* x  = (const float*)d_in[0];
    const int*   ei = (const int*)  d_in[1];
    const float* W1 = (const float*)d_in[2];
    const float* b1 = (const float*)d_in[3];
    const float* W2 = (const float*)d_in[4];
    const float* b2 = (const float*)d_in[5];
    float* out = (float*)d_out;

    const int n = in_sizes[0] / IN_F;     // 100000
    const int e = in_sizes[1] / 2;        // 3200000
    const int* src = ei;
    const int* dst = ei + e;

    const int csr_len = e + 8 * n;        // padded CSR extent actually used
    const int csr4    = (csr_len + 3) / 4;

    const int nb = (n + 255) / 256;
    const int eb = (e + 255) / 256;
    const int zb = (csr4 > n ? csr4 + 255 : n + 255) / 256;
    const int gb = (n + G1_ROWS - 1) / G1_ROWS;
    const int g4 = (4 * n + 255) / 256;

    // gemm1 deliberately at launch index 3 — the slot ncu's -s 5 -c 1 capture
    // has landed on every round — so next round finally profiles it.
    k_zero   <<<zb, 256>>>(n, csr4);
    k_hist   <<<eb, 256>>>(dst, e);
    k_scanA  <<<nb, 256>>>(n);
    k_gemm1  <<<gb, 256>>>(x, W1, n);
    k_scanC  <<<nb, 256>>>(n);
    k_fill   <<<eb, 256>>>(src, dst, e);
    k_gather1<<<g4, 256>>>(b1, W2, n);
    k_gather2<<<g4, 256>>>(b2, out, n);
}